// round 2
// baseline (speedup 1.0000x reference)
#include <cuda_runtime.h>
#include <cuda_bf16.h>
#include <cstdint>

// ---------------------------------------------------------------------------
// GCN layer: out = relu(diag(d) * A_tilde * diag(d) * H * W),  d = rowsum(A)^-1/2
// Reassociated as:  P = diag(d) * (H @ W)   (small GEMM, 8192x256x256)
//                   out = relu(diag(d) * (A @ P))  (big GEMM, 8192x256x8192)
// Big GEMM is fp32 compute-bound -> use packed fma.rn.f32x2 (2x FFMA tput).
// ---------------------------------------------------------------------------

#define NROWS 8192
#define FDIM  256

__device__ float g_d[NROWS];
__device__ float g_P[NROWS * FDIM];

// ---------------- packed f32x2 helpers ----------------
__device__ __forceinline__ uint64_t pack2dup(float v) {
    uint64_t r;
    asm("mov.b64 %0, {%1, %2};" : "=l"(r) : "f"(v), "f"(v));
    return r;
}
__device__ __forceinline__ uint64_t fma2(uint64_t a, uint64_t b, uint64_t c) {
    uint64_t d;
    asm("fma.rn.f32x2 %0, %1, %2, %3;" : "=l"(d) : "l"(a), "l"(b), "l"(c));
    return d;
}
__device__ __forceinline__ void unpack2(uint64_t v, float& lo, float& hi) {
    asm("mov.b64 {%0, %1}, %2;" : "=f"(lo), "=f"(hi) : "l"(v));
}

// ---------------- row-sum -> d = rsqrt(sum) ----------------
__global__ __launch_bounds__(256) void rowsum_kernel(const float* __restrict__ A,
                                                     float* __restrict__ d, int N) {
    __shared__ float red[8];
    const int row = blockIdx.x;
    const float4* Ar = (const float4*)(A + (size_t)row * N);
    const int n4 = N >> 2;
    float s = 0.f;
    for (int i = threadIdx.x; i < n4; i += 256) {
        float4 v = Ar[i];
        s += (v.x + v.y) + (v.z + v.w);
    }
    #pragma unroll
    for (int o = 16; o; o >>= 1) s += __shfl_xor_sync(0xffffffffu, s, o);
    if ((threadIdx.x & 31) == 0) red[threadIdx.x >> 5] = s;
    __syncthreads();
    if (threadIdx.x < 8) {
        s = red[threadIdx.x];
        #pragma unroll
        for (int o = 4; o; o >>= 1) s += __shfl_xor_sync(0xffu, s, o);
        if (threadIdx.x == 0) d[row] = rsqrtf(s);
    }
}

// ---------------- tiled SGEMM with row-scale (+optional relu) epilogue ------
// C[M,N] = epi( dvec[row] * (A[M,K] @ B[K,N]) ),  all row-major.
// BM=128, BN=64, BK=16; 256 threads; per-thread 8(M) x 4(N) via packed f32x2
// pairs along M (so A-side pairs load directly as 8B words from smem).
#define BM 128
#define BN 64
#define BK 16
#define TM 8
#define TN 4

template <int RELU>
__global__ __launch_bounds__(256) void gemm_scaled(const float* __restrict__ A,
                                                   const float* __restrict__ B,
                                                   const float* __restrict__ dvec,
                                                   float* __restrict__ C,
                                                   int M, int N, int K) {
    __shared__ float As[BK][BM];   // transposed A tile: As[k][m]
    __shared__ float Bs[BK][BN];

    const int tid = threadIdx.x;
    const int tx = tid & 15;   // N direction (0..15)
    const int ty = tid >> 4;   // M direction (0..15)
    const int bm = blockIdx.y * BM;
    const int bn = blockIdx.x * BN;

    // A tile load mapping: 128 rows x 16 cols, 2 threads/row, 8 floats each
    const int arow = tid >> 1;          // 0..127
    const int acol = (tid & 1) << 3;    // 0 or 8
    const float* Ap = A + (size_t)(bm + arow) * K + acol;

    // B tile load mapping: 16 rows x 64 cols, 1 float4/thread
    const int brow = tid >> 4;          // 0..15
    const int bcol = (tid & 15) << 2;   // 0..60
    const float* Bp = B + (size_t)brow * N + bn + bcol;

    uint64_t acc[4][TN];                // packed pairs of M-rows
    #pragma unroll
    for (int i = 0; i < 4; i++)
        #pragma unroll
        for (int j = 0; j < TN; j++) acc[i][j] = 0ull;  // (0.f, 0.f)

    // prefetch tile 0
    float4 pa0 = *(const float4*)(Ap);
    float4 pa1 = *(const float4*)(Ap + 4);
    float4 pb  = *(const float4*)(Bp);

    for (int kt = 0; kt < K; kt += BK) {
        // commit prefetched tile to smem (A transposed)
        As[acol + 0][arow] = pa0.x; As[acol + 1][arow] = pa0.y;
        As[acol + 2][arow] = pa0.z; As[acol + 3][arow] = pa0.w;
        As[acol + 4][arow] = pa1.x; As[acol + 5][arow] = pa1.y;
        As[acol + 6][arow] = pa1.z; As[acol + 7][arow] = pa1.w;
        *(float4*)&Bs[brow][bcol] = pb;
        __syncthreads();

        const int ktn = kt + BK;
        if (ktn < K) {
            pa0 = *(const float4*)(Ap + ktn);
            pa1 = *(const float4*)(Ap + ktn + 4);
            pb  = *(const float4*)(Bp + (size_t)ktn * N);
        }

        #pragma unroll
        for (int k = 0; k < BK; k++) {
            // 8 consecutive M-rows as 4 packed f32x2 words (16B-aligned LDS)
            const ulonglong2 a01 = *(const ulonglong2*)&As[k][ty * TM];
            const ulonglong2 a23 = *(const ulonglong2*)&As[k][ty * TM + 4];
            const uint64_t av[4] = {a01.x, a01.y, a23.x, a23.y};
            const float4 bv = *(const float4*)&Bs[k][tx * TN];
            uint64_t bb[4];
            bb[0] = pack2dup(bv.x); bb[1] = pack2dup(bv.y);
            bb[2] = pack2dup(bv.z); bb[3] = pack2dup(bv.w);
            #pragma unroll
            for (int i = 0; i < 4; i++)
                #pragma unroll
                for (int j = 0; j < 4; j++)
                    acc[i][j] = fma2(av[i], bb[j], acc[i][j]);
        }
        __syncthreads();
    }

    // epilogue: scale by dvec[row], optional relu, vectorized stores
    const int ccol = bn + tx * TN;
    #pragma unroll
    for (int i = 0; i < 4; i++) {
        const int r0 = bm + ty * TM + 2 * i;
        const float s0 = dvec[r0];
        const float s1 = dvec[r0 + 1];
        float lo[4], hi[4];
        #pragma unroll
        for (int j = 0; j < 4; j++) {
            unpack2(acc[i][j], lo[j], hi[j]);
            lo[j] *= s0; hi[j] *= s1;
            if (RELU) { lo[j] = fmaxf(lo[j], 0.f); hi[j] = fmaxf(hi[j], 0.f); }
        }
        *(float4*)&C[(size_t)r0 * N + ccol]       = make_float4(lo[0], lo[1], lo[2], lo[3]);
        *(float4*)&C[(size_t)(r0 + 1) * N + ccol] = make_float4(hi[0], hi[1], hi[2], hi[3]);
    }
}

// ---------------------------------------------------------------------------
extern "C" void kernel_launch(void* const* d_in, const int* in_sizes, int n_in,
                              void* d_out, int out_size) {
    // Robust input mapping by element count
    const float* H = nullptr;   // 8192*256
    const float* A = nullptr;   // 8192*8192
    const float* W = nullptr;   // 256*256
    for (int i = 0; i < n_in; i++) {
        if (in_sizes[i] == NROWS * NROWS) A = (const float*)d_in[i];
        else if (in_sizes[i] == FDIM * FDIM) W = (const float*)d_in[i];
        else if (in_sizes[i] == NROWS * FDIM) H = (const float*)d_in[i];
    }
    float* out = (float*)d_out;

    float* dptr = nullptr;
    float* Pptr = nullptr;
    cudaGetSymbolAddress((void**)&dptr, g_d);
    cudaGetSymbolAddress((void**)&Pptr, g_P);

    // 1) d = rowsum(A)^-1/2
    rowsum_kernel<<<NROWS, 256>>>(A, dptr, NROWS);

    // 2) P = diag(d) * (H @ W)    [8192 x 256]
    dim3 gridS(FDIM / BN, NROWS / BM);
    gemm_scaled<0><<<gridS, 256>>>(H, W, dptr, Pptr, NROWS, FDIM, FDIM);

    // 3) out = relu(diag(d) * (A @ P))   [8192 x 256], K = 8192
    dim3 gridB(FDIM / BN, NROWS / BM);
    gemm_scaled<1><<<gridB, 256>>>(A, Pptr, dptr, out, NROWS, FDIM, NROWS);
}

// round 4
// speedup vs baseline: 2.6076x; 2.6076x over previous
#include <cuda_runtime.h>
#include <cuda_bf16.h>
#include <cstdint>

// ============================================================================
// GCN layer on GB300 (sm_103 base target -- tcgen05 unavailable, use mma.sync):
//   d  = rowsum(A)^-1/2
//   Pt = tf32_rna( diag(d) * (H @ W) )^T     [256 x 8192]  (f32x2 GEMM)
//   out = relu( 1.000338 * diag(d) * (A @ P) )   (mma.sync tf32 GEMM)
// 1.000338 cancels the tf32 truncation bias (2^-11 * ln2) on the raw-fp32
// A operand (A ~ U(0,1)); Pt is RNA-rounded at the source (zero-mean).
// ============================================================================

#define NROWS 8192
#define FDIM  256

__device__ float g_d[NROWS];
__device__ __align__(16) float g_Pt[FDIM * NROWS];   // P^T, K-major

// ---------------- helpers ----------------
__device__ __forceinline__ uint32_t smem_u32(const void* p) {
    uint32_t a;
    asm("{ .reg .u64 t; cvta.to.shared.u64 t, %1; cvt.u32.u64 %0, t; }" : "=r"(a) : "l"(p));
    return a;
}
__device__ __forceinline__ float to_tf32(float x) {
    float r; asm("cvt.rna.tf32.f32 %0, %1;" : "=f"(r) : "f"(x)); return r;
}
__device__ __forceinline__ uint64_t pack2dup(float v) {
    uint64_t r; asm("mov.b64 %0, {%1, %2};" : "=l"(r) : "f"(v), "f"(v)); return r;
}
__device__ __forceinline__ uint64_t fma2(uint64_t a, uint64_t b, uint64_t c) {
    uint64_t d; asm("fma.rn.f32x2 %0, %1, %2, %3;" : "=l"(d) : "l"(a), "l"(b), "l"(c)); return d;
}
__device__ __forceinline__ void unpack2(uint64_t v, float& lo, float& hi) {
    asm("mov.b64 {%0, %1}, %2;" : "=f"(lo), "=f"(hi) : "l"(v));
}

#define CP_ASYNC16(sdst, gsrc) \
    asm volatile("cp.async.cg.shared.global [%0], [%1], 16;" :: "r"(sdst), "l"(gsrc) : "memory")
#define CP_COMMIT() asm volatile("cp.async.commit_group;" ::: "memory")
#define CP_WAIT3()  asm volatile("cp.async.wait_group 3;" ::: "memory")

__device__ __forceinline__ uint32_t lds32(uint32_t p) {
    uint32_t v; asm volatile("ld.shared.b32 %0, [%1];" : "=r"(v) : "r"(p)); return v;
}

// ---------------------------------------------------------------------------
// Kernel 1: d = rowsum(A)^-1/2
// ---------------------------------------------------------------------------
__global__ __launch_bounds__(256) void rowsum_kernel(const float* __restrict__ A,
                                                     float* __restrict__ d) {
    __shared__ float red[8];
    const int row = blockIdx.x;
    const float4* Ar = (const float4*)(A + (size_t)row * NROWS);
    float s = 0.f;
    for (int i = threadIdx.x; i < NROWS / 4; i += 256) {
        float4 v = Ar[i];
        s += (v.x + v.y) + (v.z + v.w);
    }
    #pragma unroll
    for (int o = 16; o; o >>= 1) s += __shfl_xor_sync(0xffffffffu, s, o);
    if ((threadIdx.x & 31) == 0) red[threadIdx.x >> 5] = s;
    __syncthreads();
    if (threadIdx.x < 8) {
        s = red[threadIdx.x];
        #pragma unroll
        for (int o = 4; o; o >>= 1) s += __shfl_xor_sync(0xffu, s, o);
        if (threadIdx.x == 0) d[row] = rsqrtf(s);
    }
}

// ---------------------------------------------------------------------------
// Kernel 2: Pt[f][k] = tf32_rna( d[k] * (H @ W)[k][f] )  -- transposed store.
// ---------------------------------------------------------------------------
#define BM 128
#define BN 64
#define BK 16
#define TM 8
#define TN 4

__global__ __launch_bounds__(256) void gemm_HW_Pt(const float* __restrict__ H,
                                                  const float* __restrict__ W,
                                                  const float* __restrict__ dvec,
                                                  float* __restrict__ Pt) {
    __shared__ float As[BK][BM];
    __shared__ float Bs[BK][BN];

    const int tid = threadIdx.x;
    const int tx = tid & 15;
    const int ty = tid >> 4;
    const int bm = blockIdx.y * BM;
    const int bn = blockIdx.x * BN;
    const int K = FDIM, Ncols = FDIM;

    const int arow = tid >> 1;
    const int acol = (tid & 1) << 3;
    const float* Ap = H + (size_t)(bm + arow) * K + acol;
    const int brow = tid >> 4;
    const int bcol = (tid & 15) << 2;
    const float* Bp = W + (size_t)brow * Ncols + bn + bcol;

    uint64_t acc[4][TN];
    #pragma unroll
    for (int i = 0; i < 4; i++)
        #pragma unroll
        for (int j = 0; j < TN; j++) acc[i][j] = 0ull;

    float4 pa0 = *(const float4*)(Ap);
    float4 pa1 = *(const float4*)(Ap + 4);
    float4 pb  = *(const float4*)(Bp);

    for (int kt = 0; kt < K; kt += BK) {
        As[acol + 0][arow] = pa0.x; As[acol + 1][arow] = pa0.y;
        As[acol + 2][arow] = pa0.z; As[acol + 3][arow] = pa0.w;
        As[acol + 4][arow] = pa1.x; As[acol + 5][arow] = pa1.y;
        As[acol + 6][arow] = pa1.z; As[acol + 7][arow] = pa1.w;
        *(float4*)&Bs[brow][bcol] = pb;
        __syncthreads();

        const int ktn = kt + BK;
        if (ktn < K) {
            pa0 = *(const float4*)(Ap + ktn);
            pa1 = *(const float4*)(Ap + ktn + 4);
            pb  = *(const float4*)(Bp + (size_t)ktn * Ncols);
        }

        #pragma unroll
        for (int k = 0; k < BK; k++) {
            const ulonglong2 a01 = *(const ulonglong2*)&As[k][ty * TM];
            const ulonglong2 a23 = *(const ulonglong2*)&As[k][ty * TM + 4];
            const uint64_t av[4] = {a01.x, a01.y, a23.x, a23.y};
            const float4 bv = *(const float4*)&Bs[k][tx * TN];
            uint64_t bb[4];
            bb[0] = pack2dup(bv.x); bb[1] = pack2dup(bv.y);
            bb[2] = pack2dup(bv.z); bb[3] = pack2dup(bv.w);
            #pragma unroll
            for (int i = 0; i < 4; i++)
                #pragma unroll
                for (int j = 0; j < 4; j++)
                    acc[i][j] = fma2(av[i], bb[j], acc[i][j]);
        }
        __syncthreads();
    }

    const int r0 = bm + ty * TM;
    float ds[8];
    #pragma unroll
    for (int r = 0; r < 8; r++) ds[r] = dvec[r0 + r];
    #pragma unroll
    for (int j = 0; j < 4; j++) {
        const int col = bn + tx * TN + j;
        float v[8];
        #pragma unroll
        for (int i = 0; i < 4; i++) unpack2(acc[i][j], v[2 * i], v[2 * i + 1]);
        #pragma unroll
        for (int r = 0; r < 8; r++) v[r] = to_tf32(v[r] * ds[r]);
        float* p = Pt + (size_t)col * NROWS + r0;
        *(float4*)p       = make_float4(v[0], v[1], v[2], v[3]);
        *(float4*)(p + 4) = make_float4(v[4], v[5], v[6], v[7]);
    }
}

// ---------------------------------------------------------------------------
// Kernel 3: out = relu( comp * d[m] * sum_k A[m][k] * Pt[n][k] )
// mma.sync tf32. Per CTA: M=128, N=128, K=8192. 256 thr = 2x4 warps of 64x32.
// 5-stage cp.async ring, K-chunk 32. SMEM rows padded to 144B (bank-clean).
// ---------------------------------------------------------------------------
#define NS 5
#define KT 32
#define NITER (NROWS / KT)       // 256
#define ROWB 144                 // padded row stride in bytes (32 floats + 16B)
#define TILE_B (128 * ROWB)      // 18432
#define STG_B (2 * TILE_B)       // 36864
#define SMEM_BIG (NS * STG_B)    // 184320

__global__ __launch_bounds__(256, 1) void spmm_mma(const float* __restrict__ A,
                                                   const float* __restrict__ Pt,
                                                   const float* __restrict__ dvec,
                                                   float* __restrict__ out) {
    extern __shared__ char smem[];
    const uint32_t sb = smem_u32(smem);
    const int tid = threadIdx.x;
    const int lane = tid & 31;
    const int wid = tid >> 5;
    const int warp_m = wid >> 2;          // 0..1
    const int warp_n = wid & 3;           // 0..3
    const int bm = (int)blockIdx.y * 128;
    const int bn = (int)blockIdx.x * 128;

    // per-thread cp.async slots: 4 chunks of 16B per tile (A and B)
    uint32_t dst[4];
    const char* asrc[4];
    const char* bsrc[4];
    #pragma unroll
    for (int i = 0; i < 4; i++) {
        const int idx = tid + 256 * i;    // 0..1023
        const int r = idx >> 3, c = idx & 7;
        dst[i] = (uint32_t)(r * ROWB + c * 16);
        asrc[i] = (const char*)(A  + (size_t)(bm + r) * NROWS) + c * 16;
        bsrc[i] = (const char*)(Pt + (size_t)(bn + r) * NROWS) + c * 16;
    }

    auto load_stage = [&](int s, int it) {
        const uint32_t base = sb + s * STG_B;
        const size_t koff = (size_t)it * (KT * 4);
        #pragma unroll
        for (int i = 0; i < 4; i++) CP_ASYNC16(base + dst[i], asrc[i] + koff);
        #pragma unroll
        for (int i = 0; i < 4; i++) CP_ASYNC16(base + TILE_B + dst[i], bsrc[i] + koff);
    };

    float acc[4][4][4];
    #pragma unroll
    for (int mt = 0; mt < 4; mt++)
        #pragma unroll
        for (int nt = 0; nt < 4; nt++)
            #pragma unroll
            for (int q = 0; q < 4; q++) acc[mt][nt][q] = 0.f;

    // prologue: stages 0..NS-2
    #pragma unroll
    for (int j = 0; j < NS - 1; j++) { load_stage(j, j); CP_COMMIT(); }

    const uint32_t a_lane_off = (uint32_t)((warp_m * 64 + (lane >> 2)) * ROWB + (lane & 3) * 4);
    const uint32_t b_lane_off = (uint32_t)(TILE_B + (warp_n * 32 + (lane >> 2)) * ROWB + (lane & 3) * 4);

    for (int it = 0; it < NITER; it++) {
        CP_WAIT3();                 // stage 'it' resident
        __syncthreads();

        const uint32_t stage = sb + (it % NS) * STG_B;
        #pragma unroll
        for (int k0 = 0; k0 < KT; k0 += 8) {
            uint32_t a[4][4];
            #pragma unroll
            for (int mt = 0; mt < 4; mt++) {
                const uint32_t p = stage + a_lane_off + mt * (16 * ROWB) + k0 * 4;
                a[mt][0] = lds32(p);
                a[mt][1] = lds32(p + 8 * ROWB);
                a[mt][2] = lds32(p + 16);
                a[mt][3] = lds32(p + 8 * ROWB + 16);
            }
            uint32_t b[4][2];
            #pragma unroll
            for (int nt = 0; nt < 4; nt++) {
                const uint32_t p = stage + b_lane_off + nt * (8 * ROWB) + k0 * 4;
                b[nt][0] = lds32(p);
                b[nt][1] = lds32(p + 16);
            }
            #pragma unroll
            for (int mt = 0; mt < 4; mt++)
                #pragma unroll
                for (int nt = 0; nt < 4; nt++)
                    asm volatile(
                        "mma.sync.aligned.m16n8k8.row.col.f32.tf32.tf32.f32 "
                        "{%0,%1,%2,%3}, {%4,%5,%6,%7}, {%8,%9}, {%0,%1,%2,%3};"
                        : "+f"(acc[mt][nt][0]), "+f"(acc[mt][nt][1]),
                          "+f"(acc[mt][nt][2]), "+f"(acc[mt][nt][3])
                        : "r"(a[mt][0]), "r"(a[mt][1]), "r"(a[mt][2]), "r"(a[mt][3]),
                          "r"(b[nt][0]), "r"(b[nt][1]));
        }
        __syncthreads();

        const int j = it + NS - 1;
        if (j < NITER) load_stage(j % NS, j);
        CP_COMMIT();                // empty groups in tail keep FIFO numbering exact
    }

    // epilogue: scale by comp*d[row], relu, float2 stores
    #pragma unroll
    for (int mt = 0; mt < 4; mt++) {
        const int r0 = bm + warp_m * 64 + mt * 16 + (lane >> 2);
        const float s0 = 1.000338f * dvec[r0];
        const float s1 = 1.000338f * dvec[r0 + 8];
        #pragma unroll
        for (int nt = 0; nt < 4; nt++) {
            const int col = bn + warp_n * 32 + nt * 8 + (lane & 3) * 2;
            float2 v0, v1;
            v0.x = fmaxf(s0 * acc[mt][nt][0], 0.f);
            v0.y = fmaxf(s0 * acc[mt][nt][1], 0.f);
            v1.x = fmaxf(s1 * acc[mt][nt][2], 0.f);
            v1.y = fmaxf(s1 * acc[mt][nt][3], 0.f);
            *(float2*)(out + (size_t)r0 * FDIM + col)       = v0;
            *(float2*)(out + (size_t)(r0 + 8) * FDIM + col) = v1;
        }
    }
}

// ---------------------------------------------------------------------------
extern "C" void kernel_launch(void* const* d_in, const int* in_sizes, int n_in,
                              void* d_out, int out_size) {
    const float* H = nullptr;
    const float* A = nullptr;
    const float* W = nullptr;
    for (int i = 0; i < n_in; i++) {
        if (in_sizes[i] == NROWS * NROWS) A = (const float*)d_in[i];
        else if (in_sizes[i] == FDIM * FDIM) W = (const float*)d_in[i];
        else if (in_sizes[i] == NROWS * FDIM) H = (const float*)d_in[i];
    }
    float* out = (float*)d_out;

    float* dptr = nullptr;
    float* Ptp = nullptr;
    cudaGetSymbolAddress((void**)&dptr, g_d);
    cudaGetSymbolAddress((void**)&Ptp, g_Pt);

    cudaFuncSetAttribute(spmm_mma, cudaFuncAttributeMaxDynamicSharedMemorySize, SMEM_BIG);

    // 1) d = rowsum(A)^-1/2
    rowsum_kernel<<<NROWS, 256>>>(A, dptr);

    // 2) Pt = tf32( diag(d) * (H @ W) )^T   [256 x 8192]
    dim3 gridS(FDIM / BN, NROWS / BM);
    gemm_HW_Pt<<<gridS, 256>>>(H, W, dptr, Ptp);

    // 3) out = relu(comp * diag(d) * (A @ P))  via mma.sync tf32
    dim3 gridB(2, NROWS / 128);
    spmm_mma<<<gridB, 256, SMEM_BIG>>>(A, Ptp, dptr, out);
}

// round 5
// speedup vs baseline: 4.0707x; 1.5611x over previous
#include <cuda_runtime.h>
#include <cuda_fp16.h>
#include <cstdint>

// ============================================================================
// GCN layer on GB300 (sm_103 base target):
//   d, Ah = rowsum(A)^-1/2  and  fp16(A)        (fused single pass over A)
//   Pth   = fp16_rn( diag(d) * (H @ W) )^T      (f32x2 GEMM, K-major store)
//   out   = relu( diag(d) * (Ah @ Pth^T) )      (mma.sync m16n8k16 fp16)
// fp16 and tf32 share the 10-bit mantissa; with RN on both operands and a
// zero-mean P, output rel_err ~ sqrt(2)*u_rms ~ 3e-4 (N-independent).
// ============================================================================

#define NROWS 8192
#define FDIM  256

__device__ float g_d[NROWS];
__device__ __align__(16) __half g_Ah[(size_t)NROWS * NROWS];   // fp16 A, 128MB
__device__ __align__(16) __half g_Pth[FDIM * NROWS];           // P^T fp16, K-major

// ---------------- helpers ----------------
__device__ __forceinline__ uint32_t smem_u32(const void* p) {
    uint32_t a;
    asm("{ .reg .u64 t; cvta.to.shared.u64 t, %1; cvt.u32.u64 %0, t; }" : "=r"(a) : "l"(p));
    return a;
}
__device__ __forceinline__ uint64_t pack2dup(float v) {
    uint64_t r; asm("mov.b64 %0, {%1, %2};" : "=l"(r) : "f"(v), "f"(v)); return r;
}
__device__ __forceinline__ uint64_t fma2(uint64_t a, uint64_t b, uint64_t c) {
    uint64_t d; asm("fma.rn.f32x2 %0, %1, %2, %3;" : "=l"(d) : "l"(a), "l"(b), "l"(c)); return d;
}
__device__ __forceinline__ void unpack2(uint64_t v, float& lo, float& hi) {
    asm("mov.b64 {%0, %1}, %2;" : "=f"(lo), "=f"(hi) : "l"(v));
}
__device__ __forceinline__ uint32_t h2u(__half2 h) {
    uint32_t u; asm("mov.b32 %0, %1;" : "=r"(u) : "r"(*(uint32_t*)&h)); return u;
}

#define CP_ASYNC16(sdst, gsrc) \
    asm volatile("cp.async.cg.shared.global [%0], [%1], 16;" :: "r"(sdst), "l"(gsrc) : "memory")
#define CP_COMMIT() asm volatile("cp.async.commit_group;" ::: "memory")
#define CP_WAIT3()  asm volatile("cp.async.wait_group 3;" ::: "memory")

__device__ __forceinline__ uint32_t lds32(uint32_t p) {
    uint32_t v; asm volatile("ld.shared.b32 %0, [%1];" : "=r"(v) : "r"(p)); return v;
}

// ---------------------------------------------------------------------------
// Kernel 1: d = rowsum(A)^-1/2, and Ah = fp16_rn(A).  One pass over A.
// ---------------------------------------------------------------------------
__global__ __launch_bounds__(256) void rowsum_convert(const float* __restrict__ A,
                                                      float* __restrict__ d,
                                                      __half* __restrict__ Ah) {
    __shared__ float red[8];
    const int row = blockIdx.x;
    const float4* Ar = (const float4*)(A + (size_t)row * NROWS);
    uint2* Hr = (uint2*)(Ah + (size_t)row * NROWS);
    float s = 0.f;
    #pragma unroll
    for (int i = 0; i < 8; i++) {             // 8 * 256 * 4 = 8192 floats
        const int idx = threadIdx.x + 256 * i;
        float4 v = Ar[idx];
        s += (v.x + v.y) + (v.z + v.w);
        __half2 h01 = __floats2half2_rn(v.x, v.y);
        __half2 h23 = __floats2half2_rn(v.z, v.w);
        uint2 u;
        u.x = *(uint32_t*)&h01;
        u.y = *(uint32_t*)&h23;
        Hr[idx] = u;
    }
    #pragma unroll
    for (int o = 16; o; o >>= 1) s += __shfl_xor_sync(0xffffffffu, s, o);
    if ((threadIdx.x & 31) == 0) red[threadIdx.x >> 5] = s;
    __syncthreads();
    if (threadIdx.x < 8) {
        s = red[threadIdx.x];
        #pragma unroll
        for (int o = 4; o; o >>= 1) s += __shfl_xor_sync(0xffu, s, o);
        if (threadIdx.x == 0) d[row] = rsqrtf(s);
    }
}

// ---------------------------------------------------------------------------
// Kernel 2: Pth[f][k] = fp16_rn( d[k] * (H @ W)[k][f] )  -- transposed store.
// f32x2-packed SGEMM, BM=128 BN=64 BK=16, 256 threads, 8x4 per thread.
// ---------------------------------------------------------------------------
#define BM 128
#define BN 64
#define BK 16
#define TM 8
#define TN 4

__global__ __launch_bounds__(256) void gemm_HW_Pt(const float* __restrict__ H,
                                                  const float* __restrict__ W,
                                                  const float* __restrict__ dvec,
                                                  __half* __restrict__ Pth) {
    __shared__ float As[BK][BM];
    __shared__ float Bs[BK][BN];

    const int tid = threadIdx.x;
    const int tx = tid & 15;
    const int ty = tid >> 4;
    const int bm = blockIdx.y * BM;
    const int bn = blockIdx.x * BN;
    const int K = FDIM, Ncols = FDIM;

    const int arow = tid >> 1;
    const int acol = (tid & 1) << 3;
    const float* Ap = H + (size_t)(bm + arow) * K + acol;
    const int brow = tid >> 4;
    const int bcol = (tid & 15) << 2;
    const float* Bp = W + (size_t)brow * Ncols + bn + bcol;

    uint64_t acc[4][TN];
    #pragma unroll
    for (int i = 0; i < 4; i++)
        #pragma unroll
        for (int j = 0; j < TN; j++) acc[i][j] = 0ull;

    float4 pa0 = *(const float4*)(Ap);
    float4 pa1 = *(const float4*)(Ap + 4);
    float4 pb  = *(const float4*)(Bp);

    for (int kt = 0; kt < K; kt += BK) {
        As[acol + 0][arow] = pa0.x; As[acol + 1][arow] = pa0.y;
        As[acol + 2][arow] = pa0.z; As[acol + 3][arow] = pa0.w;
        As[acol + 4][arow] = pa1.x; As[acol + 5][arow] = pa1.y;
        As[acol + 6][arow] = pa1.z; As[acol + 7][arow] = pa1.w;
        *(float4*)&Bs[brow][bcol] = pb;
        __syncthreads();

        const int ktn = kt + BK;
        if (ktn < K) {
            pa0 = *(const float4*)(Ap + ktn);
            pa1 = *(const float4*)(Ap + ktn + 4);
            pb  = *(const float4*)(Bp + (size_t)ktn * Ncols);
        }

        #pragma unroll
        for (int k = 0; k < BK; k++) {
            const ulonglong2 a01 = *(const ulonglong2*)&As[k][ty * TM];
            const ulonglong2 a23 = *(const ulonglong2*)&As[k][ty * TM + 4];
            const uint64_t av[4] = {a01.x, a01.y, a23.x, a23.y};
            const float4 bv = *(const float4*)&Bs[k][tx * TN];
            uint64_t bb[4];
            bb[0] = pack2dup(bv.x); bb[1] = pack2dup(bv.y);
            bb[2] = pack2dup(bv.z); bb[3] = pack2dup(bv.w);
            #pragma unroll
            for (int i = 0; i < 4; i++)
                #pragma unroll
                for (int j = 0; j < 4; j++)
                    acc[i][j] = fma2(av[i], bb[j], acc[i][j]);
        }
        __syncthreads();
    }

    // transposed epilogue: 8 consecutive k-rows -> one 16B fp16 store
    const int r0 = bm + ty * TM;
    float ds[8];
    #pragma unroll
    for (int r = 0; r < 8; r++) ds[r] = dvec[r0 + r];
    #pragma unroll
    for (int j = 0; j < 4; j++) {
        const int col = bn + tx * TN + j;
        float v[8];
        #pragma unroll
        for (int i = 0; i < 4; i++) unpack2(acc[i][j], v[2 * i], v[2 * i + 1]);
        #pragma unroll
        for (int r = 0; r < 8; r++) v[r] *= ds[r];
        __half2 h0 = __floats2half2_rn(v[0], v[1]);
        __half2 h1 = __floats2half2_rn(v[2], v[3]);
        __half2 h2 = __floats2half2_rn(v[4], v[5]);
        __half2 h3 = __floats2half2_rn(v[6], v[7]);
        uint4 u;
        u.x = *(uint32_t*)&h0; u.y = *(uint32_t*)&h1;
        u.z = *(uint32_t*)&h2; u.w = *(uint32_t*)&h3;
        *(uint4*)(Pth + (size_t)col * NROWS + r0) = u;
    }
}

// ---------------------------------------------------------------------------
// Kernel 3: out = relu( d[m] * sum_k Ah[m][k] * Pth[n][k] )
// mma.sync.m16n8k16 fp16. Per CTA: M=128, N=128, K=8192. 2x4 warps of 64x32.
// 5-stage cp.async ring, K-chunk 64 halves. Rows padded to 144B (bank-clean).
// Single __syncthreads per iter; loads issued before compute.
// ---------------------------------------------------------------------------
#define NS 5
#define KT 64                    // halves per K-chunk
#define NITER (NROWS / KT)       // 128
#define ROWB 144                 // row stride bytes (128B data + 16B pad)
#define TILE_B (128 * ROWB)      // 18432
#define STG_B (2 * TILE_B)       // 36864
#define SMEM_BIG (NS * STG_B)    // 184320

__global__ __launch_bounds__(256, 1) void spmm_mma(const __half* __restrict__ Ah,
                                                   const __half* __restrict__ Pth,
                                                   const float* __restrict__ dvec,
                                                   float* __restrict__ out) {
    extern __shared__ char smem[];
    const uint32_t sb = smem_u32(smem);
    const int tid = threadIdx.x;
    const int lane = tid & 31;
    const int wid = tid >> 5;
    const int warp_m = wid >> 2;          // 0..1
    const int warp_n = wid & 3;           // 0..3
    const int bm = (int)blockIdx.y * 128;
    const int bn = (int)blockIdx.x * 128;

    // per-thread cp.async slots: 4 x 16B per operand tile (128 rows x 8 chunks)
    uint32_t dst[4];
    const char* asrc[4];
    const char* bsrc[4];
    #pragma unroll
    for (int i = 0; i < 4; i++) {
        const int idx = tid + 256 * i;    // 0..1023
        const int r = idx >> 3, c = idx & 7;
        dst[i] = (uint32_t)(r * ROWB + c * 16);
        asrc[i] = (const char*)(Ah  + (size_t)(bm + r) * NROWS) + c * 16;
        bsrc[i] = (const char*)(Pth + (size_t)(bn + r) * NROWS) + c * 16;
    }

    auto load_stage = [&](int s, int it) {
        const uint32_t base = sb + s * STG_B;
        const size_t koff = (size_t)it * (KT * 2);   // bytes
        #pragma unroll
        for (int i = 0; i < 4; i++) CP_ASYNC16(base + dst[i], asrc[i] + koff);
        #pragma unroll
        for (int i = 0; i < 4; i++) CP_ASYNC16(base + TILE_B + dst[i], bsrc[i] + koff);
    };

    float acc[4][4][4];
    #pragma unroll
    for (int mt = 0; mt < 4; mt++)
        #pragma unroll
        for (int nt = 0; nt < 4; nt++)
            #pragma unroll
            for (int q = 0; q < 4; q++) acc[mt][nt][q] = 0.f;

    // prologue: stages 0..NS-2
    #pragma unroll
    for (int j = 0; j < NS - 1; j++) { load_stage(j, j); CP_COMMIT(); }

    // lane base offsets (bytes): A row = warp_m*64 + lane/4, k = (lane%4)*2 halves
    const uint32_t a_lane_off = (uint32_t)((warp_m * 64 + (lane >> 2)) * ROWB + (lane & 3) * 4);
    const uint32_t b_lane_off = (uint32_t)(TILE_B + (warp_n * 32 + (lane >> 2)) * ROWB + (lane & 3) * 4);

    for (int it = 0; it < NITER; it++) {
        CP_WAIT3();                 // stage 'it' resident
        __syncthreads();            // also: all warps done computing stage it-1

        const int j = it + NS - 1;
        if (j < NITER) load_stage(j % NS, j);   // overwrites stage (it-1)%NS
        CP_COMMIT();                // empty groups in tail keep FIFO numbering exact

        const uint32_t stage = sb + (it % NS) * STG_B;
        #pragma unroll
        for (int kc = 0; kc < 4; kc++) {        // k0 = kc*16 halves
            const uint32_t kb = (uint32_t)(kc * 32);   // bytes
            uint32_t a[4][4];
            #pragma unroll
            for (int mt = 0; mt < 4; mt++) {
                const uint32_t p = stage + a_lane_off + mt * (16 * ROWB) + kb;
                a[mt][0] = lds32(p);
                a[mt][1] = lds32(p + 8 * ROWB);
                a[mt][2] = lds32(p + 16);
                a[mt][3] = lds32(p + 8 * ROWB + 16);
            }
            uint32_t b[4][2];
            #pragma unroll
            for (int nt = 0; nt < 4; nt++) {
                const uint32_t p = stage + b_lane_off + nt * (8 * ROWB) + kb;
                b[nt][0] = lds32(p);
                b[nt][1] = lds32(p + 16);
            }
            #pragma unroll
            for (int mt = 0; mt < 4; mt++)
                #pragma unroll
                for (int nt = 0; nt < 4; nt++)
                    asm volatile(
                        "mma.sync.aligned.m16n8k16.row.col.f32.f16.f16.f32 "
                        "{%0,%1,%2,%3}, {%4,%5,%6,%7}, {%8,%9}, {%0,%1,%2,%3};"
                        : "+f"(acc[mt][nt][0]), "+f"(acc[mt][nt][1]),
                          "+f"(acc[mt][nt][2]), "+f"(acc[mt][nt][3])
                        : "r"(a[mt][0]), "r"(a[mt][1]), "r"(a[mt][2]), "r"(a[mt][3]),
                          "r"(b[nt][0]), "r"(b[nt][1]));
        }
    }

    // epilogue: scale by d[row], relu, float2 stores
    #pragma unroll
    for (int mt = 0; mt < 4; mt++) {
        const int r0 = bm + warp_m * 64 + mt * 16 + (lane >> 2);
        const float s0 = dvec[r0];
        const float s1 = dvec[r0 + 8];
        #pragma unroll
        for (int nt = 0; nt < 4; nt++) {
            const int col = bn + warp_n * 32 + nt * 8 + (lane & 3) * 2;
            float2 v0, v1;
            v0.x = fmaxf(s0 * acc[mt][nt][0], 0.f);
            v0.y = fmaxf(s0 * acc[mt][nt][1], 0.f);
            v1.x = fmaxf(s1 * acc[mt][nt][2], 0.f);
            v1.y = fmaxf(s1 * acc[mt][nt][3], 0.f);
            *(float2*)(out + (size_t)r0 * FDIM + col)       = v0;
            *(float2*)(out + (size_t)(r0 + 8) * FDIM + col) = v1;
        }
    }
}

// ---------------------------------------------------------------------------
extern "C" void kernel_launch(void* const* d_in, const int* in_sizes, int n_in,
                              void* d_out, int out_size) {
    const float* H = nullptr;
    const float* A = nullptr;
    const float* W = nullptr;
    for (int i = 0; i < n_in; i++) {
        if (in_sizes[i] == NROWS * NROWS) A = (const float*)d_in[i];
        else if (in_sizes[i] == FDIM * FDIM) W = (const float*)d_in[i];
        else if (in_sizes[i] == NROWS * FDIM) H = (const float*)d_in[i];
    }
    float* out = (float*)d_out;

    float* dptr = nullptr;
    __half* Ahp = nullptr;
    __half* Ptp = nullptr;
    cudaGetSymbolAddress((void**)&dptr, g_d);
    cudaGetSymbolAddress((void**)&Ahp, g_Ah);
    cudaGetSymbolAddress((void**)&Ptp, g_Pth);

    cudaFuncSetAttribute(spmm_mma, cudaFuncAttributeMaxDynamicSharedMemorySize, SMEM_BIG);

    // 1) d = rowsum(A)^-1/2  and  Ah = fp16(A)
    rowsum_convert<<<NROWS, 256>>>(A, dptr, Ahp);

    // 2) Pth = fp16( diag(d) * (H @ W) )^T   [256 x 8192]
    dim3 gridS(FDIM / BN, NROWS / BM);
    gemm_HW_Pt<<<gridS, 256>>>(H, W, dptr, Ptp);

    // 3) out = relu(diag(d) * (Ah @ P))  via mma.sync fp16
    dim3 gridB(2, NROWS / 128);
    spmm_mma<<<gridB, 256, SMEM_BIG>>>(Ahp, Ptp, dptr, out);
}

// round 7
// speedup vs baseline: 4.3131x; 1.0596x over previous
#include <cuda_runtime.h>
#include <cuda_fp16.h>
#include <cstdint>

// ============================================================================
// GCN layer on GB300 (sm_103 base target):
//   FUSED:  blocks 0..255   : Qt = (H @ W)^T          (f32x2 GEMM, no d needed)
//           blocks 256..8447: d = rowsum(A)^-1/2, Ah = fp16(A)
//           (DRAM-bound and fma-bound halves run concurrently in one launch)
//   scaleP: Pth[f][k] = fp16( d[k] * Qt[f][k] )
//   spmm  : out = relu( diag(d) * (Ah @ Pth^T) )      (mma.sync m16n8k16)
// ============================================================================

#define NROWS 8192
#define FDIM  256

__device__ float g_d[NROWS];
__device__ __align__(16) __half g_Ah[(size_t)NROWS * NROWS];   // fp16 A, 128MB
__device__ __align__(16) float  g_Qt[FDIM * NROWS];            // (HW)^T fp32, 8MB
__device__ __align__(16) __half g_Pth[FDIM * NROWS];           // P^T fp16, K-major

// ---------------- helpers ----------------
__device__ __forceinline__ uint32_t smem_u32(const void* p) {
    uint32_t a;
    asm("{ .reg .u64 t; cvta.to.shared.u64 t, %1; cvt.u32.u64 %0, t; }" : "=r"(a) : "l"(p));
    return a;
}
__device__ __forceinline__ uint64_t pack2dup(float v) {
    uint64_t r; asm("mov.b64 %0, {%1, %2};" : "=l"(r) : "f"(v), "f"(v)); return r;
}
__device__ __forceinline__ uint64_t fma2(uint64_t a, uint64_t b, uint64_t c) {
    uint64_t d; asm("fma.rn.f32x2 %0, %1, %2, %3;" : "=l"(d) : "l"(a), "l"(b), "l"(c)); return d;
}
__device__ __forceinline__ void unpack2(uint64_t v, float& lo, float& hi) {
    asm("mov.b64 {%0, %1}, %2;" : "=f"(lo), "=f"(hi) : "l"(v));
}

#define CP_ASYNC16(sdst, gsrc) \
    asm volatile("cp.async.cg.shared.global [%0], [%1], 16;" :: "r"(sdst), "l"(gsrc) : "memory")
#define CP_COMMIT() asm volatile("cp.async.commit_group;" ::: "memory")
#define CP_WAIT3()  asm volatile("cp.async.wait_group 3;" ::: "memory")

__device__ __forceinline__ uint32_t lds32(uint32_t p) {
    uint32_t v; asm volatile("ld.shared.b32 %0, [%1];" : "=r"(v) : "r"(p)); return v;
}

// ---------------------------------------------------------------------------
// Fused kernel: blocks 0..255 -> Qt tile (128x64 of H@W, transposed store),
//               blocks 256..8447 -> rowsum+convert of row (bid-256).
// GEMM blocks launch first so they co-schedule with the DRAM-bound wave.
// ---------------------------------------------------------------------------
#define BM 128
#define BN 64
#define BK 16
#define TM 8
#define TN 4
#define GEMM_BLOCKS 256   // (FDIM/BN) * (NROWS/BM) = 4 * 64

__global__ __launch_bounds__(256) void fused_pre(const float* __restrict__ A,
                                                 const float* __restrict__ H,
                                                 const float* __restrict__ W,
                                                 float* __restrict__ d,
                                                 __half* __restrict__ Ah,
                                                 float* __restrict__ Qt) {
    __shared__ float As[BK][BM];
    __shared__ float Bs[BK][BN];
    __shared__ float red[8];

    const int tid = threadIdx.x;

    if (blockIdx.x >= GEMM_BLOCKS) {
        // ---------------- rowsum + fp16 convert ----------------
        const int row = blockIdx.x - GEMM_BLOCKS;
        const float4* Ar = (const float4*)(A + (size_t)row * NROWS);
        uint2* Hr = (uint2*)(Ah + (size_t)row * NROWS);
        float s = 0.f;
        #pragma unroll
        for (int i = 0; i < 8; i++) {
            const int idx = tid + 256 * i;
            float4 v = Ar[idx];
            s += (v.x + v.y) + (v.z + v.w);
            __half2 h01 = __floats2half2_rn(v.x, v.y);
            __half2 h23 = __floats2half2_rn(v.z, v.w);
            uint2 u;
            u.x = *(uint32_t*)&h01;
            u.y = *(uint32_t*)&h23;
            Hr[idx] = u;
        }
        #pragma unroll
        for (int o = 16; o; o >>= 1) s += __shfl_xor_sync(0xffffffffu, s, o);
        if ((tid & 31) == 0) red[tid >> 5] = s;
        __syncthreads();
        if (tid < 8) {
            s = red[tid];
            #pragma unroll
            for (int o = 4; o; o >>= 1) s += __shfl_xor_sync(0xffu, s, o);
            if (tid == 0) d[row] = rsqrtf(s);
        }
        return;
    }

    // ---------------- small GEMM: Qt = (H @ W)^T (unscaled) ----------------
    const int tx = tid & 15;
    const int ty = tid >> 4;
    const int bm = (int)(blockIdx.x >> 2) * BM;     // 0..63 -> M
    const int bn = (int)(blockIdx.x & 3) * BN;      // 0..3  -> N
    const int K = FDIM, Ncols = FDIM;

    const int arow = tid >> 1;
    const int acol = (tid & 1) << 3;
    const float* Ap = H + (size_t)(bm + arow) * K + acol;
    const int brow = tid >> 4;
    const int bcol = (tid & 15) << 2;
    const float* Bp = W + (size_t)brow * Ncols + bn + bcol;

    uint64_t acc[4][TN];
    #pragma unroll
    for (int i = 0; i < 4; i++)
        #pragma unroll
        for (int j = 0; j < TN; j++) acc[i][j] = 0ull;

    float4 pa0 = *(const float4*)(Ap);
    float4 pa1 = *(const float4*)(Ap + 4);
    float4 pb  = *(const float4*)(Bp);

    for (int kt = 0; kt < K; kt += BK) {
        As[acol + 0][arow] = pa0.x; As[acol + 1][arow] = pa0.y;
        As[acol + 2][arow] = pa0.z; As[acol + 3][arow] = pa0.w;
        As[acol + 4][arow] = pa1.x; As[acol + 5][arow] = pa1.y;
        As[acol + 6][arow] = pa1.z; As[acol + 7][arow] = pa1.w;
        *(float4*)&Bs[brow][bcol] = pb;
        __syncthreads();

        const int ktn = kt + BK;
        if (ktn < K) {
            pa0 = *(const float4*)(Ap + ktn);
            pa1 = *(const float4*)(Ap + ktn + 4);
            pb  = *(const float4*)(Bp + (size_t)ktn * Ncols);
        }

        #pragma unroll
        for (int k = 0; k < BK; k++) {
            const ulonglong2 a01 = *(const ulonglong2*)&As[k][ty * TM];
            const ulonglong2 a23 = *(const ulonglong2*)&As[k][ty * TM + 4];
            const uint64_t av[4] = {a01.x, a01.y, a23.x, a23.y};
            const float4 bv = *(const float4*)&Bs[k][tx * TN];
            uint64_t bb[4];
            bb[0] = pack2dup(bv.x); bb[1] = pack2dup(bv.y);
            bb[2] = pack2dup(bv.z); bb[3] = pack2dup(bv.w);
            #pragma unroll
            for (int i = 0; i < 4; i++)
                #pragma unroll
                for (int j = 0; j < 4; j++)
                    acc[i][j] = fma2(av[i], bb[j], acc[i][j]);
        }
        __syncthreads();
    }

    // transposed fp32 store (unscaled): Qt[col][bm+ty*8 .. +7]
    const int r0 = bm + ty * TM;
    #pragma unroll
    for (int j = 0; j < 4; j++) {
        const int col = bn + tx * TN + j;
        float v[8];
        #pragma unroll
        for (int i = 0; i < 4; i++) unpack2(acc[i][j], v[2 * i], v[2 * i + 1]);
        float* p = Qt + (size_t)col * NROWS + r0;
        *(float4*)p       = make_float4(v[0], v[1], v[2], v[3]);
        *(float4*)(p + 4) = make_float4(v[4], v[5], v[6], v[7]);
    }
}

// ---------------------------------------------------------------------------
// scaleP: Pth[f][k] = fp16( d[k] * Qt[f][k] ).  8 elems / thread.
// ---------------------------------------------------------------------------
__global__ __launch_bounds__(256) void scaleP(const float* __restrict__ Qt,
                                              const float* __restrict__ dvec,
                                              __half* __restrict__ Pth) {
    const size_t base = ((size_t)blockIdx.x * 256 + threadIdx.x) * 8;
    const size_t k = base & (NROWS - 1);           // NROWS divides row stride
    float4 q0 = *(const float4*)(Qt + base);
    float4 q1 = *(const float4*)(Qt + base + 4);
    float4 d0 = *(const float4*)(dvec + k);
    float4 d1 = *(const float4*)(dvec + k + 4);
    __half2 h0 = __floats2half2_rn(q0.x * d0.x, q0.y * d0.y);
    __half2 h1 = __floats2half2_rn(q0.z * d0.z, q0.w * d0.w);
    __half2 h2 = __floats2half2_rn(q1.x * d1.x, q1.y * d1.y);
    __half2 h3 = __floats2half2_rn(q1.z * d1.z, q1.w * d1.w);
    uint4 u;
    u.x = *(uint32_t*)&h0; u.y = *(uint32_t*)&h1;
    u.z = *(uint32_t*)&h2; u.w = *(uint32_t*)&h3;
    *(uint4*)(Pth + base) = u;
}

// ---------------------------------------------------------------------------
// spmm: out = relu( d[m] * sum_k Ah[m][k] * Pth[n][k] )   (unchanged from R5)
// ---------------------------------------------------------------------------
#define NS 5
#define KT 64
#define NITER (NROWS / KT)
#define ROWB 144
#define TILE_B (128 * ROWB)
#define STG_B (2 * TILE_B)
#define SMEM_BIG (NS * STG_B)

__global__ __launch_bounds__(256, 1) void spmm_mma(const __half* __restrict__ Ah,
                                                   const __half* __restrict__ Pth,
                                                   const float* __restrict__ dvec,
                                                   float* __restrict__ out) {
    extern __shared__ char smem[];
    const uint32_t sb = smem_u32(smem);
    const int tid = threadIdx.x;
    const int lane = tid & 31;
    const int wid = tid >> 5;
    const int warp_m = wid >> 2;
    const int warp_n = wid & 3;
    const int bm = (int)blockIdx.y * 128;
    const int bn = (int)blockIdx.x * 128;

    uint32_t dst[4];
    const char* asrc[4];
    const char* bsrc[4];
    #pragma unroll
    for (int i = 0; i < 4; i++) {
        const int idx = tid + 256 * i;
        const int r = idx >> 3, c = idx & 7;
        dst[i] = (uint32_t)(r * ROWB + c * 16);
        asrc[i] = (const char*)(Ah  + (size_t)(bm + r) * NROWS) + c * 16;
        bsrc[i] = (const char*)(Pth + (size_t)(bn + r) * NROWS) + c * 16;
    }

    auto load_stage = [&](int s, int it) {
        const uint32_t base = sb + s * STG_B;
        const size_t koff = (size_t)it * (KT * 2);
        #pragma unroll
        for (int i = 0; i < 4; i++) CP_ASYNC16(base + dst[i], asrc[i] + koff);
        #pragma unroll
        for (int i = 0; i < 4; i++) CP_ASYNC16(base + TILE_B + dst[i], bsrc[i] + koff);
    };

    float acc[4][4][4];
    #pragma unroll
    for (int mt = 0; mt < 4; mt++)
        #pragma unroll
        for (int nt = 0; nt < 4; nt++)
            #pragma unroll
            for (int q = 0; q < 4; q++) acc[mt][nt][q] = 0.f;

    #pragma unroll
    for (int j = 0; j < NS - 1; j++) { load_stage(j, j); CP_COMMIT(); }

    const uint32_t a_lane_off = (uint32_t)((warp_m * 64 + (lane >> 2)) * ROWB + (lane & 3) * 4);
    const uint32_t b_lane_off = (uint32_t)(TILE_B + (warp_n * 32 + (lane >> 2)) * ROWB + (lane & 3) * 4);

    for (int it = 0; it < NITER; it++) {
        CP_WAIT3();
        __syncthreads();

        const int j = it + NS - 1;
        if (j < NITER) load_stage(j % NS, j);
        CP_COMMIT();

        const uint32_t stage = sb + (it % NS) * STG_B;
        #pragma unroll
        for (int kc = 0; kc < 4; kc++) {
            const uint32_t kb = (uint32_t)(kc * 32);
            uint32_t a[4][4];
            #pragma unroll
            for (int mt = 0; mt < 4; mt++) {
                const uint32_t p = stage + a_lane_off + mt * (16 * ROWB) + kb;
                a[mt][0] = lds32(p);
                a[mt][1] = lds32(p + 8 * ROWB);
                a[mt][2] = lds32(p + 16);
                a[mt][3] = lds32(p + 8 * ROWB + 16);
            }
            uint32_t b[4][2];
            #pragma unroll
            for (int nt = 0; nt < 4; nt++) {
                const uint32_t p = stage + b_lane_off + nt * (8 * ROWB) + kb;
                b[nt][0] = lds32(p);
                b[nt][1] = lds32(p + 16);
            }
            #pragma unroll
            for (int mt = 0; mt < 4; mt++)
                #pragma unroll
                for (int nt = 0; nt < 4; nt++)
                    asm volatile(
                        "mma.sync.aligned.m16n8k16.row.col.f32.f16.f16.f32 "
                        "{%0,%1,%2,%3}, {%4,%5,%6,%7}, {%8,%9}, {%0,%1,%2,%3};"
                        : "+f"(acc[mt][nt][0]), "+f"(acc[mt][nt][1]),
                          "+f"(acc[mt][nt][2]), "+f"(acc[mt][nt][3])
                        : "r"(a[mt][0]), "r"(a[mt][1]), "r"(a[mt][2]), "r"(a[mt][3]),
                          "r"(b[nt][0]), "r"(b[nt][1]));
        }
    }

    #pragma unroll
    for (int mt = 0; mt < 4; mt++) {
        const int r0 = bm + warp_m * 64 + mt * 16 + (lane >> 2);
        const float s0 = dvec[r0];
        const float s1 = dvec[r0 + 8];
        #pragma unroll
        for (int nt = 0; nt < 4; nt++) {
            const int col = bn + warp_n * 32 + nt * 8 + (lane & 3) * 2;
            float2 v0, v1;
            v0.x = fmaxf(s0 * acc[mt][nt][0], 0.f);
            v0.y = fmaxf(s0 * acc[mt][nt][1], 0.f);
            v1.x = fmaxf(s1 * acc[mt][nt][2], 0.f);
            v1.y = fmaxf(s1 * acc[mt][nt][3], 0.f);
            *(float2*)(out + (size_t)r0 * FDIM + col)       = v0;
            *(float2*)(out + (size_t)(r0 + 8) * FDIM + col) = v1;
        }
    }
}

// ---------------------------------------------------------------------------
extern "C" void kernel_launch(void* const* d_in, const int* in_sizes, int n_in,
                              void* d_out, int out_size) {
    const float* H = nullptr;
    const float* A = nullptr;
    const float* W = nullptr;
    for (int i = 0; i < n_in; i++) {
        if (in_sizes[i] == NROWS * NROWS) A = (const float*)d_in[i];
        else if (in_sizes[i] == FDIM * FDIM) W = (const float*)d_in[i];
        else if (in_sizes[i] == NROWS * FDIM) H = (const float*)d_in[i];
    }
    float* out = (float*)d_out;

    float* dptr = nullptr;
    __half* Ahp = nullptr;
    float* Qtp = nullptr;
    __half* Ptp = nullptr;
    cudaGetSymbolAddress((void**)&dptr, g_d);
    cudaGetSymbolAddress((void**)&Ahp, g_Ah);
    cudaGetSymbolAddress((void**)&Qtp, g_Qt);
    cudaGetSymbolAddress((void**)&Ptp, g_Pth);

    cudaFuncSetAttribute(spmm_mma, cudaFuncAttributeMaxDynamicSharedMemorySize, SMEM_BIG);

    // 1) fused: Qt = (H@W)^T  ||  d = rowsum(A)^-1/2, Ah = fp16(A)
    fused_pre<<<GEMM_BLOCKS + NROWS, 256>>>(A, H, W, dptr, Ahp, Qtp);

    // 2) Pth = fp16(diag-k scale of Qt)
    scaleP<<<(FDIM * NROWS) / (256 * 8), 256>>>(Qtp, dptr, Ptp);

    // 3) out = relu(diag(d) * (Ah @ P))  via mma.sync fp16
    dim3 gridB(2, NROWS / 128);
    spmm_mma<<<gridB, 256, SMEM_BIG>>>(Ahp, Ptp, dptr, out);
}